// round 1
// baseline (speedup 1.0000x reference)
#include <cuda_runtime.h>
#include <cuda_bf16.h>
#include <math.h>

// ---------------- model constants ----------------
#define Vv 50257
#define Dd 768
#define Hh 12
#define HD 64
#define Tt 1024
#define Ll 6
#define Bb 4
#define BT (Bb*Tt)          // 4096
#define FF (4*Dd)           // 3072

// ---------------- scratch (static device arrays; no allocation) ----------------
__device__ float g_x  [BT*Dd];
__device__ float g_x2 [BT*Dd];
__device__ float g_q  [BT*Dd];
__device__ float g_k  [BT*Dd];
__device__ float g_v  [BT*Dd];
__device__ float g_y  [BT*Dd];
__device__ float g_ff1[BT*FF];
__device__ float g_rl [BT];

// ---------------- embedding ----------------
__global__ void embed_kernel(const int* __restrict__ idx,
                             const float* __restrict__ tok,
                             const float* __restrict__ pos,
                             float* __restrict__ x) {
    int r = blockIdx.x;            // 0..BT-1
    int t = r & (Tt - 1);
    int token = idx[r];
    const float* tr = tok + (size_t)token * Dd;
    const float* pr = pos + (size_t)t * Dd;
    float* xr = x + (size_t)r * Dd;
    for (int c = threadIdx.x; c < Dd; c += blockDim.x)
        xr[c] = tr[c] + pr[c];
}

// ---------------- SGEMM: C = A(MxK) @ B(KxN) [+bias] [+relu] ----------------
// EPI: 0 = none, 1 = +bias, 2 = +bias, relu
template<int EPI>
__global__ __launch_bounds__(256)
void sgemm_kernel(const float* __restrict__ A, const float* __restrict__ Bm,
                  const float* __restrict__ bias, float* __restrict__ C,
                  int M, int N, int K) {
    const int BM = 128, BN = 128, BK = 8;
    __shared__ float As[BK][BM];
    __shared__ float Bs[BK][BN];

    int t  = threadIdx.x;          // 0..255
    int tx = t & 15;               // col group
    int ty = t >> 4;               // row group
    int bx = blockIdx.x, by = blockIdx.y;

    int row0 = by * BM;
    int col0 = bx * BN;

    float acc[8][8];
#pragma unroll
    for (int i = 0; i < 8; i++)
#pragma unroll
        for (int j = 0; j < 8; j++) acc[i][j] = 0.f;

    // A-load mapping: each thread loads one float4 (row = t/2, seg = t%2)
    int arow = t >> 1;
    int aseg = (t & 1) * 4;

    for (int k0 = 0; k0 < K; k0 += BK) {
        // load A tile (K divisible by 8, rows always in-range: M multiple of 128)
        {
            const float4 a4 = *(const float4*)(A + (size_t)(row0 + arow) * K + k0 + aseg);
            As[aseg + 0][arow] = a4.x;
            As[aseg + 1][arow] = a4.y;
            As[aseg + 2][arow] = a4.z;
            As[aseg + 3][arow] = a4.w;
        }
        // load B tile, scalar with column guard (N may be 50257)
#pragma unroll
        for (int u = 0; u < 4; u++) {
            int idx = t * 4 + u;
            int kr = idx >> 7;          // 0..7
            int c  = idx & 127;
            int col = col0 + c;
            Bs[kr][c] = (col < N) ? Bm[(size_t)(k0 + kr) * N + col] : 0.f;
        }
        __syncthreads();

#pragma unroll
        for (int kk = 0; kk < BK; kk++) {
            float a[8], b[8];
            float4 a0 = *(float4*)&As[kk][ty * 8];
            float4 a1 = *(float4*)&As[kk][ty * 8 + 4];
            float4 b0 = *(float4*)&Bs[kk][tx * 8];
            float4 b1 = *(float4*)&Bs[kk][tx * 8 + 4];
            a[0]=a0.x; a[1]=a0.y; a[2]=a0.z; a[3]=a0.w;
            a[4]=a1.x; a[5]=a1.y; a[6]=a1.z; a[7]=a1.w;
            b[0]=b0.x; b[1]=b0.y; b[2]=b0.z; b[3]=b0.w;
            b[4]=b1.x; b[5]=b1.y; b[6]=b1.z; b[7]=b1.w;
#pragma unroll
            for (int i = 0; i < 8; i++)
#pragma unroll
                for (int j = 0; j < 8; j++)
                    acc[i][j] += a[i] * b[j];
        }
        __syncthreads();
    }

    int r0 = row0 + ty * 8;
    int c0 = col0 + tx * 8;
#pragma unroll
    for (int i = 0; i < 8; i++) {
        long long rbase = (long long)(r0 + i) * N;
#pragma unroll
        for (int j = 0; j < 8; j++) {
            int col = c0 + j;
            if (col < N) {
                float vv = acc[i][j];
                if (EPI >= 1) vv += bias[col];
                if (EPI == 2) vv = fmaxf(vv, 0.f);
                C[rbase + col] = vv;
            }
        }
    }
}

// ---------------- causal flash attention ----------------
// grid: (T/64, H, B), block: 128 threads
__global__ __launch_bounds__(128)
void attn_kernel(const float* __restrict__ q, const float* __restrict__ k,
                 const float* __restrict__ v, float* __restrict__ y) {
    __shared__ float Qs[64][65];
    __shared__ float Ks[32][65];
    __shared__ float Vs[32][65];
    __shared__ float Ss[64][33];
    __shared__ float mrow[64], lrow[64], cfac[64];

    int t  = threadIdx.x;
    int qt = blockIdx.x;
    int h  = blockIdx.y;
    int b  = blockIdx.z;
    int q0 = qt * 64;

    // load Q tile
    for (int idx = t; idx < 64 * 64; idx += 128) {
        int r = idx >> 6, c = idx & 63;
        Qs[r][c] = q[((size_t)(b * Tt + q0 + r)) * Dd + h * HD + c];
    }
    if (t < 64) { mrow[t] = -1e30f; lrow[t] = 0.f; }

    float acc[32];
#pragma unroll
    for (int d = 0; d < 32; d++) acc[d] = 0.f;

    int qi_own = t & 63;
    int hoff   = (t >> 6) * 32;

    int ntiles = (q0 + 64) / 32;
    __syncthreads();

    for (int j = 0; j < ntiles; j++) {
        int s0 = j * 32;
        for (int idx = t; idx < 32 * 64; idx += 128) {
            int r = idx >> 6, c = idx & 63;
            size_t g = ((size_t)(b * Tt + s0 + r)) * Dd + h * HD + c;
            Ks[r][c] = k[g];
            Vs[r][c] = v[g];
        }
        __syncthreads();

        // scores S = Q K^T / 8, causal mask
        for (int idx = t; idx < 64 * 32; idx += 128) {
            int qi = idx >> 5, kj = idx & 31;
            float sum = 0.f;
#pragma unroll
            for (int c = 0; c < 64; c++) sum += Qs[qi][c] * Ks[kj][c];
            sum *= 0.125f;
            if (s0 + kj > q0 + qi) sum = -1e30f;
            Ss[qi][kj] = sum;
        }
        __syncthreads();

        // online softmax update (one thread per query)
        if (t < 64) {
            int qi = t;
            float m = mrow[qi];
            float nm = m;
#pragma unroll
            for (int kj = 0; kj < 32; kj++) nm = fmaxf(nm, Ss[qi][kj]);
            float corr = __expf(m - nm);
            float sum = 0.f;
#pragma unroll
            for (int kj = 0; kj < 32; kj++) {
                float p = __expf(Ss[qi][kj] - nm);
                Ss[qi][kj] = p;
                sum += p;
            }
            lrow[qi] = lrow[qi] * corr + sum;
            mrow[qi] = nm;
            cfac[qi] = corr;
        }
        __syncthreads();

        // acc = acc*corr + P @ V
        float corr = cfac[qi_own];
#pragma unroll
        for (int d = 0; d < 32; d++) acc[d] *= corr;
#pragma unroll
        for (int kj = 0; kj < 32; kj++) {
            float p = Ss[qi_own][kj];
#pragma unroll
            for (int d = 0; d < 32; d++)
                acc[d] += p * Vs[kj][hoff + d];
        }
        __syncthreads();
    }

    float inv = 1.f / lrow[qi_own];
    size_t base = ((size_t)(b * Tt + q0 + qi_own)) * Dd + h * HD + hoff;
#pragma unroll
    for (int d = 0; d < 32; d++)
        y[base + d] = acc[d] * inv;
}

// ---------------- residual + LayerNorm: out = LN(a + b) * g + beta ----------------
__global__ __launch_bounds__(256)
void ln_res_kernel(const float* __restrict__ a, const float* __restrict__ b,
                   const float* __restrict__ g, const float* __restrict__ be,
                   float* __restrict__ out) {
    __shared__ float buf[Dd];
    __shared__ float red[256];
    int r = blockIdx.x;
    int t = threadIdx.x;
    const float* ar = a + (size_t)r * Dd;
    const float* br = b + (size_t)r * Dd;

    float s = 0.f;
    for (int c = t; c < Dd; c += 256) {
        float vv = ar[c] + br[c];
        buf[c] = vv;
        s += vv;
    }
    red[t] = s; __syncthreads();
    for (int o = 128; o > 0; o >>= 1) { if (t < o) red[t] += red[t + o]; __syncthreads(); }
    float mu = red[0] / (float)Dd;
    __syncthreads();

    float s2 = 0.f;
    for (int c = t; c < Dd; c += 256) {
        float d = buf[c] - mu;
        s2 += d * d;
    }
    red[t] = s2; __syncthreads();
    for (int o = 128; o > 0; o >>= 1) { if (t < o) red[t] += red[t + o]; __syncthreads(); }
    float rstd = rsqrtf(red[0] / (float)Dd + 1e-5f);

    float* orr = out + (size_t)r * Dd;
    for (int c = t; c < Dd; c += 256)
        orr[c] = (buf[c] - mu) * rstd * g[c] + be[c];
}

// ---------------- per-row cross-entropy (online logsumexp) ----------------
__global__ __launch_bounds__(256)
void rowloss_kernel(const float* __restrict__ logits, const int* __restrict__ tgt,
                    float* __restrict__ rl) {
    __shared__ float sm[256], sl[256];
    int r = blockIdx.x;
    int t = threadIdx.x;
    const float* lg = logits + (size_t)r * Vv;

    float m = -1e30f, l = 0.f;
    for (int c = t; c < Vv; c += 256) {
        float x = lg[c];
        if (x > m) { l = l * __expf(m - x) + 1.f; m = x; }
        else       { l += __expf(x - m); }
    }
    sm[t] = m; sl[t] = l; __syncthreads();
    for (int o = 128; o > 0; o >>= 1) {
        if (t < o) {
            float m1 = sm[t], m2 = sm[t + o];
            float M = fmaxf(m1, m2);
            sl[t] = sl[t] * __expf(m1 - M) + sl[t + o] * __expf(m2 - M);
            sm[t] = M;
        }
        __syncthreads();
    }
    if (t == 0)
        rl[r] = (sm[0] + logf(sl[0])) - lg[tgt[r]];
}

__global__ __launch_bounds__(256)
void meanloss_kernel(const float* __restrict__ rl, float* __restrict__ out) {
    __shared__ float red[256];
    int t = threadIdx.x;
    float s = 0.f;
    for (int i = t; i < BT; i += 256) s += rl[i];
    red[t] = s; __syncthreads();
    for (int o = 128; o > 0; o >>= 1) { if (t < o) red[t] += red[t + o]; __syncthreads(); }
    if (t == 0) out[0] = red[0] / (float)BT;
}

// ---------------- launch ----------------
extern "C" void kernel_launch(void* const* d_in, const int* in_sizes, int n_in,
                              void* d_out, int out_size) {
    const int*   idx    = (const int*)  d_in[0];
    const int*   tgt    = (const int*)  d_in[1];
    const float* tok    = (const float*)d_in[2];
    const float* pos    = (const float*)d_in[3];
    const float* Wq     = (const float*)d_in[4];
    const float* Wk     = (const float*)d_in[5];
    const float* Wv     = (const float*)d_in[6];
    const float* ln1g   = (const float*)d_in[7];
    const float* ln1b   = (const float*)d_in[8];
    const float* W1     = (const float*)d_in[9];
    const float* b1     = (const float*)d_in[10];
    const float* W2     = (const float*)d_in[11];
    const float* b2     = (const float*)d_in[12];
    const float* ln2g   = (const float*)d_in[13];
    const float* ln2b   = (const float*)d_in[14];
    const float* headw  = (const float*)d_in[15];
    const float* headb  = (const float*)d_in[16];
    float* out = (float*)d_out;

    float *x, *x2, *q, *k, *v, *y, *ff1, *rl;
    cudaGetSymbolAddress((void**)&x,   g_x);
    cudaGetSymbolAddress((void**)&x2,  g_x2);
    cudaGetSymbolAddress((void**)&q,   g_q);
    cudaGetSymbolAddress((void**)&k,   g_k);
    cudaGetSymbolAddress((void**)&v,   g_v);
    cudaGetSymbolAddress((void**)&y,   g_y);
    cudaGetSymbolAddress((void**)&ff1, g_ff1);
    cudaGetSymbolAddress((void**)&rl,  g_rl);

    embed_kernel<<<BT, 256>>>(idx, tok, pos, x);

    dim3 gD((Dd + 127) / 128, BT / 128);     // N=768
    dim3 gF((FF + 127) / 128, BT / 128);     // N=3072
    dim3 gV((Vv + 127) / 128, BT / 128);     // N=50257

    for (int l = 0; l < Ll; l++) {
        const float* wq = Wq + (size_t)l * Dd * Dd;
        const float* wk = Wk + (size_t)l * Dd * Dd;
        const float* wv = Wv + (size_t)l * Dd * Dd;
        const float* w1 = W1 + (size_t)l * Dd * FF;
        const float* w2 = W2 + (size_t)l * FF * Dd;

        sgemm_kernel<0><<<gD, 256>>>(x, wq, nullptr, q, BT, Dd, Dd);
        sgemm_kernel<0><<<gD, 256>>>(x, wk, nullptr, k, BT, Dd, Dd);
        sgemm_kernel<0><<<gD, 256>>>(x, wv, nullptr, v, BT, Dd, Dd);

        attn_kernel<<<dim3(Tt / 64, Hh, Bb), 128>>>(q, k, v, y);

        ln_res_kernel<<<BT, 256>>>(y, x, ln1g + l * Dd, ln1b + l * Dd, x2);

        sgemm_kernel<2><<<gF, 256>>>(x2, w1, b1 + (size_t)l * FF, ff1, BT, FF, Dd);
        sgemm_kernel<1><<<gD, 256>>>(ff1, w2, b2 + (size_t)l * Dd, y, BT, Dd, FF);

        ln_res_kernel<<<BT, 256>>>(y, x2, ln2g + l * Dd, ln2b + l * Dd, x);
    }

    // logits -> d_out (first BT*V floats)
    sgemm_kernel<1><<<gV, 256>>>(x, headw, headb, out, BT, Vv, Dd);

    // loss -> d_out[BT*V]
    rowloss_kernel<<<BT, 256>>>(out, tgt, rl);
    meanloss_kernel<<<1, 256>>>(rl, out + (size_t)BT * Vv);
}

// round 3
// speedup vs baseline: 3.3328x; 3.3328x over previous
#include <cuda_runtime.h>
#include <cuda_bf16.h>
#include <math.h>

// ---------------- model constants ----------------
#define Vv 50257
#define Dd 768
#define Hh 12
#define HD 64
#define Tt 1024
#define Ll 6
#define Bb 4
#define BT (Bb*Tt)          // 4096
#define FF (4*Dd)           // 3072

// ---------------- scratch (static device arrays; no allocation) ----------------
__device__ float g_x  [BT*Dd];
__device__ float g_x2 [BT*Dd];
__device__ float g_q  [BT*Dd];
__device__ float g_k  [BT*Dd];
__device__ float g_v  [BT*Dd];
__device__ float g_y  [BT*Dd];
__device__ float g_ff1[BT*FF];
__device__ float g_rl [BT];

__device__ __forceinline__ float to_tf32(float x) {
    float y;
    asm("cvt.rna.tf32.f32 %0, %1;" : "=f"(y) : "f"(x));
    return y;
}

// ---------------- embedding ----------------
__global__ void embed_kernel(const int* __restrict__ idx,
                             const float* __restrict__ tok,
                             const float* __restrict__ pos,
                             float* __restrict__ x) {
    int r = blockIdx.x;
    int t = r & (Tt - 1);
    int token = idx[r];
    const float* tr = tok + (size_t)token * Dd;
    const float* pr = pos + (size_t)t * Dd;
    float* xr = x + (size_t)r * Dd;
    for (int c = threadIdx.x; c < Dd; c += blockDim.x)
        xr[c] = tr[c] + pr[c];
}

// ---------------- TF32 tensor-core GEMM: C = A(MxK) @ B(KxN) [+bias][+relu] ----------------
// BM=128, BN=128, BK=16. 256 threads = 8 warps (2 along M x 4 along N).
// Warp tile 64x32 = 4 m16-subtiles x 4 n8-subtiles, mma.m16n8k8.tf32.
// EPI: 0 = none, 1 = +bias, 2 = +bias+relu
template<int EPI>
__global__ __launch_bounds__(256)
void tgemm_kernel(const float* __restrict__ A, const float* __restrict__ Bm,
                  const float* __restrict__ bias, float* __restrict__ C,
                  int M, int N, int K) {
    const int BM = 128, BN = 128, BK = 16;
    __shared__ float As[BK][BM + 4];   // As[k][m]
    __shared__ float Bs[BK][BN + 4];   // Bs[k][n]

    int t    = threadIdx.x;
    int wid  = t >> 5;
    int lane = t & 31;
    int g    = lane >> 2;      // groupID
    int tig  = lane & 3;       // thread in group

    int wm = wid & 1;          // 0..1 -> M offset
    int wn = wid >> 1;         // 0..3 -> N offset
    int m0w = wm * 64;
    int n0w = wn * 32;

    int row0 = blockIdx.y * BM;
    int col0 = blockIdx.x * BN;
    // vector path requires: full tile in range AND 16B-aligned B rows (N % 4 == 0)
    bool vec_ok = ((col0 + BN) <= N) && ((N & 3) == 0);

    float acc[4][4][4];        // [im][in][c0..c3]
#pragma unroll
    for (int im = 0; im < 4; im++)
#pragma unroll
        for (int in = 0; in < 4; in++)
#pragma unroll
            for (int c = 0; c < 4; c++) acc[im][in][c] = 0.f;

    for (int k0 = 0; k0 < K; k0 += BK) {
        // ---- load A tile: 128x16, float4 per thread x2, transpose to As[k][m] ----
        // (A strides K are 768/3072: 16B-aligned row starts, always safe)
#pragma unroll
        for (int i = 0; i < 2; i++) {
            int idx = t + i * 256;          // 0..511
            int row = idx >> 2;             // 0..127
            int seg = (idx & 3) * 4;        // 0,4,8,12
            float4 a4 = *(const float4*)(A + (size_t)(row0 + row) * K + k0 + seg);
            As[seg + 0][row] = to_tf32(a4.x);
            As[seg + 1][row] = to_tf32(a4.y);
            As[seg + 2][row] = to_tf32(a4.z);
            As[seg + 3][row] = to_tf32(a4.w);
        }
        // ---- load B tile: 16x128 ----
        if (vec_ok) {
#pragma unroll
            for (int i = 0; i < 2; i++) {
                int idx = t + i * 256;      // 0..511
                int kr  = idx >> 5;         // 0..15
                int cs  = (idx & 31) * 4;   // 0..124
                float4 b4 = *(const float4*)(Bm + (size_t)(k0 + kr) * N + col0 + cs);
                Bs[kr][cs + 0] = to_tf32(b4.x);
                Bs[kr][cs + 1] = to_tf32(b4.y);
                Bs[kr][cs + 2] = to_tf32(b4.z);
                Bs[kr][cs + 3] = to_tf32(b4.w);
            }
        } else {
#pragma unroll
            for (int i = 0; i < 8; i++) {
                int e = t + i * 256;        // 0..2047
                int kr = e >> 7;            // 0..15
                int c  = e & 127;
                int col = col0 + c;
                Bs[kr][c] = (col < N) ? to_tf32(Bm[(size_t)(k0 + kr) * N + col]) : 0.f;
            }
        }
        __syncthreads();

#pragma unroll
        for (int ks = 0; ks < BK; ks += 8) {
            // load fragments
            unsigned af[4][4], bf[4][2];
#pragma unroll
            for (int im = 0; im < 4; im++) {
                int m = m0w + im * 16 + g;
                af[im][0] = __float_as_uint(As[ks + tig    ][m    ]);
                af[im][1] = __float_as_uint(As[ks + tig    ][m + 8]);
                af[im][2] = __float_as_uint(As[ks + tig + 4][m    ]);
                af[im][3] = __float_as_uint(As[ks + tig + 4][m + 8]);
            }
#pragma unroll
            for (int in = 0; in < 4; in++) {
                int n = n0w + in * 8 + g;
                bf[in][0] = __float_as_uint(Bs[ks + tig    ][n]);
                bf[in][1] = __float_as_uint(Bs[ks + tig + 4][n]);
            }
#pragma unroll
            for (int im = 0; im < 4; im++)
#pragma unroll
                for (int in = 0; in < 4; in++) {
                    asm volatile(
                        "mma.sync.aligned.m16n8k8.row.col.f32.tf32.tf32.f32 "
                        "{%0,%1,%2,%3},{%4,%5,%6,%7},{%8,%9},{%0,%1,%2,%3};"
                        : "+f"(acc[im][in][0]), "+f"(acc[im][in][1]),
                          "+f"(acc[im][in][2]), "+f"(acc[im][in][3])
                        : "r"(af[im][0]), "r"(af[im][1]), "r"(af[im][2]), "r"(af[im][3]),
                          "r"(bf[in][0]), "r"(bf[in][1]));
                }
        }
        __syncthreads();
    }

    // ---- epilogue (scalar stores; always safe) ----
#pragma unroll
    for (int im = 0; im < 4; im++) {
        int r_lo = row0 + m0w + im * 16 + g;
        int r_hi = r_lo + 8;
#pragma unroll
        for (int in = 0; in < 4; in++) {
            int c_lo = col0 + n0w + in * 8 + 2 * tig;
            int c_hi = c_lo + 1;
            float v0 = acc[im][in][0], v1 = acc[im][in][1];
            float v2 = acc[im][in][2], v3 = acc[im][in][3];
            if (EPI >= 1) {
                if (c_lo < N) { v0 += bias[c_lo]; v2 += bias[c_lo]; }
                if (c_hi < N) { v1 += bias[c_hi]; v3 += bias[c_hi]; }
            }
            if (EPI == 2) {
                v0 = fmaxf(v0, 0.f); v1 = fmaxf(v1, 0.f);
                v2 = fmaxf(v2, 0.f); v3 = fmaxf(v3, 0.f);
            }
            size_t blo = (size_t)r_lo * N;
            size_t bhi = (size_t)r_hi * N;
            if (c_lo < N) { C[blo + c_lo] = v0; C[bhi + c_lo] = v2; }
            if (c_hi < N) { C[blo + c_hi] = v1; C[bhi + c_hi] = v3; }
        }
    }
}

// ---------------- causal flash attention ----------------
__global__ __launch_bounds__(128)
void attn_kernel(const float* __restrict__ q, const float* __restrict__ k,
                 const float* __restrict__ v, float* __restrict__ y) {
    __shared__ float Qs[64][65];
    __shared__ float Ks[32][65];
    __shared__ float Vs[32][65];
    __shared__ float Ss[64][33];
    __shared__ float mrow[64], lrow[64], cfac[64];

    int t  = threadIdx.x;
    int qt = blockIdx.x;
    int h  = blockIdx.y;
    int b  = blockIdx.z;
    int q0 = qt * 64;

    for (int idx = t; idx < 64 * 64; idx += 128) {
        int r = idx >> 6, c = idx & 63;
        Qs[r][c] = q[((size_t)(b * Tt + q0 + r)) * Dd + h * HD + c];
    }
    if (t < 64) { mrow[t] = -1e30f; lrow[t] = 0.f; }

    float acc[32];
#pragma unroll
    for (int d = 0; d < 32; d++) acc[d] = 0.f;

    int qi_own = t & 63;
    int hoff   = (t >> 6) * 32;

    int ntiles = (q0 + 64) / 32;
    __syncthreads();

    for (int j = 0; j < ntiles; j++) {
        int s0 = j * 32;
        for (int idx = t; idx < 32 * 64; idx += 128) {
            int r = idx >> 6, c = idx & 63;
            size_t gg = ((size_t)(b * Tt + s0 + r)) * Dd + h * HD + c;
            Ks[r][c] = k[gg];
            Vs[r][c] = v[gg];
        }
        __syncthreads();

        for (int idx = t; idx < 64 * 32; idx += 128) {
            int qi = idx >> 5, kj = idx & 31;
            float sum = 0.f;
#pragma unroll
            for (int c = 0; c < 64; c++) sum += Qs[qi][c] * Ks[kj][c];
            sum *= 0.125f;
            if (s0 + kj > q0 + qi) sum = -1e30f;
            Ss[qi][kj] = sum;
        }
        __syncthreads();

        if (t < 64) {
            int qi = t;
            float m = mrow[qi];
            float nm = m;
#pragma unroll
            for (int kj = 0; kj < 32; kj++) nm = fmaxf(nm, Ss[qi][kj]);
            float corr = __expf(m - nm);
            float sum = 0.f;
#pragma unroll
            for (int kj = 0; kj < 32; kj++) {
                float p = __expf(Ss[qi][kj] - nm);
                Ss[qi][kj] = p;
                sum += p;
            }
            lrow[qi] = lrow[qi] * corr + sum;
            mrow[qi] = nm;
            cfac[qi] = corr;
        }
        __syncthreads();

        float corr = cfac[qi_own];
#pragma unroll
        for (int d = 0; d < 32; d++) acc[d] *= corr;
#pragma unroll
        for (int kj = 0; kj < 32; kj++) {
            float p = Ss[qi_own][kj];
#pragma unroll
            for (int d = 0; d < 32; d++)
                acc[d] += p * Vs[kj][hoff + d];
        }
        __syncthreads();
    }

    float inv = 1.f / lrow[qi_own];
    size_t base = ((size_t)(b * Tt + q0 + qi_own)) * Dd + h * HD + hoff;
#pragma unroll
    for (int d = 0; d < 32; d++)
        y[base + d] = acc[d] * inv;
}

// ---------------- residual + LayerNorm ----------------
__global__ __launch_bounds__(256)
void ln_res_kernel(const float* __restrict__ a, const float* __restrict__ b,
                   const float* __restrict__ g, const float* __restrict__ be,
                   float* __restrict__ out) {
    __shared__ float buf[Dd];
    __shared__ float red[256];
    int r = blockIdx.x;
    int t = threadIdx.x;
    const float* ar = a + (size_t)r * Dd;
    const float* br = b + (size_t)r * Dd;

    float s = 0.f;
    for (int c = t; c < Dd; c += 256) {
        float vv = ar[c] + br[c];
        buf[c] = vv;
        s += vv;
    }
    red[t] = s; __syncthreads();
    for (int o = 128; o > 0; o >>= 1) { if (t < o) red[t] += red[t + o]; __syncthreads(); }
    float mu = red[0] / (float)Dd;
    __syncthreads();

    float s2 = 0.f;
    for (int c = t; c < Dd; c += 256) {
        float d = buf[c] - mu;
        s2 += d * d;
    }
    red[t] = s2; __syncthreads();
    for (int o = 128; o > 0; o >>= 1) { if (t < o) red[t] += red[t + o]; __syncthreads(); }
    float rstd = rsqrtf(red[0] / (float)Dd + 1e-5f);

    float* orr = out + (size_t)r * Dd;
    for (int c = t; c < Dd; c += 256)
        orr[c] = (buf[c] - mu) * rstd * g[c] + be[c];
}

// ---------------- per-row cross-entropy ----------------
__global__ __launch_bounds__(256)
void rowloss_kernel(const float* __restrict__ logits, const int* __restrict__ tgt,
                    float* __restrict__ rl) {
    __shared__ float sm[256], sl[256];
    int r = blockIdx.x;
    int t = threadIdx.x;
    const float* lg = logits + (size_t)r * Vv;

    float m = -1e30f, l = 0.f;
    for (int c = t; c < Vv; c += 256) {
        float x = lg[c];
        if (x > m) { l = l * __expf(m - x) + 1.f; m = x; }
        else       { l += __expf(x - m); }
    }
    sm[t] = m; sl[t] = l; __syncthreads();
    for (int o = 128; o > 0; o >>= 1) {
        if (t < o) {
            float m1 = sm[t], m2 = sm[t + o];
            float M = fmaxf(m1, m2);
            sl[t] = sl[t] * __expf(m1 - M) + sl[t + o] * __expf(m2 - M);
            sm[t] = M;
        }
        __syncthreads();
    }
    if (t == 0)
        rl[r] = (sm[0] + logf(sl[0])) - lg[tgt[r]];
}

__global__ __launch_bounds__(256)
void meanloss_kernel(const float* __restrict__ rl, float* __restrict__ out) {
    __shared__ float red[256];
    int t = threadIdx.x;
    float s = 0.f;
    for (int i = t; i < BT; i += 256) s += rl[i];
    red[t] = s; __syncthreads();
    for (int o = 128; o > 0; o >>= 1) { if (t < o) red[t] += red[t + o]; __syncthreads(); }
    if (t == 0) out[0] = red[0] / (float)BT;
}

// ---------------- launch ----------------
extern "C" void kernel_launch(void* const* d_in, const int* in_sizes, int n_in,
                              void* d_out, int out_size) {
    const int*   idx    = (const int*)  d_in[0];
    const int*   tgt    = (const int*)  d_in[1];
    const float* tok    = (const float*)d_in[2];
    const float* pos    = (const float*)d_in[3];
    const float* Wq     = (const float*)d_in[4];
    const float* Wk     = (const float*)d_in[5];
    const float* Wv     = (const float*)d_in[6];
    const float* ln1g   = (const float*)d_in[7];
    const float* ln1b   = (const float*)d_in[8];
    const float* W1     = (const float*)d_in[9];
    const float* b1     = (const float*)d_in[10];
    const float* W2     = (const float*)d_in[11];
    const float* b2     = (const float*)d_in[12];
    const float* ln2g   = (const float*)d_in[13];
    const float* ln2b   = (const float*)d_in[14];
    const float* headw  = (const float*)d_in[15];
    const float* headb  = (const float*)d_in[16];
    float* out = (float*)d_out;

    float *x, *x2, *q, *k, *v, *y, *ff1, *rl;
    cudaGetSymbolAddress((void**)&x,   g_x);
    cudaGetSymbolAddress((void**)&x2,  g_x2);
    cudaGetSymbolAddress((void**)&q,   g_q);
    cudaGetSymbolAddress((void**)&k,   g_k);
    cudaGetSymbolAddress((void**)&v,   g_v);
    cudaGetSymbolAddress((void**)&y,   g_y);
    cudaGetSymbolAddress((void**)&ff1, g_ff1);
    cudaGetSymbolAddress((void**)&rl,  g_rl);

    embed_kernel<<<BT, 256>>>(idx, tok, pos, x);

    dim3 gD((Dd + 127) / 128, BT / 128);     // N=768
    dim3 gF((FF + 127) / 128, BT / 128);     // N=3072
    dim3 gV((Vv + 127) / 128, BT / 128);     // N=50257

    for (int l = 0; l < Ll; l++) {
        const float* wq = Wq + (size_t)l * Dd * Dd;
        const float* wk = Wk + (size_t)l * Dd * Dd;
        const float* wv = Wv + (size_t)l * Dd * Dd;
        const float* w1 = W1 + (size_t)l * Dd * FF;
        const float* w2 = W2 + (size_t)l * FF * Dd;

        tgemm_kernel<0><<<gD, 256>>>(x, wq, nullptr, q, BT, Dd, Dd);
        tgemm_kernel<0><<<gD, 256>>>(x, wk, nullptr, k, BT, Dd, Dd);
        tgemm_kernel<0><<<gD, 256>>>(x, wv, nullptr, v, BT, Dd, Dd);

        attn_kernel<<<dim3(Tt / 64, Hh, Bb), 128>>>(q, k, v, y);

        ln_res_kernel<<<BT, 256>>>(y, x, ln1g + l * Dd, ln1b + l * Dd, x2);

        tgemm_kernel<2><<<gF, 256>>>(x2, w1, b1 + (size_t)l * FF, ff1, BT, FF, Dd);
        tgemm_kernel<1><<<gD, 256>>>(ff1, w2, b2 + (size_t)l * Dd, y, BT, Dd, FF);

        ln_res_kernel<<<BT, 256>>>(y, x2, ln2g + l * Dd, ln2b + l * Dd, x);
    }

    tgemm_kernel<1><<<gV, 256>>>(x, headw, headb, out, BT, Vv, Dd);

    rowloss_kernel<<<BT, 256>>>(out, tgt, rl);
    meanloss_kernel<<<1, 256>>>(rl, out + (size_t)BT * Vv);
}